// round 6
// baseline (speedup 1.0000x reference)
#include <cuda_runtime.h>
#include <cuda_bf16.h>
#include <cstdint>

#define Bb 4
#define Nn 4096
#define Cc 64
#define Hh 4
#define DH 16
#define KNNk 10
#define KSk 4
#define Mm 256
#define ROWS_TOT (Bb * Nn)

// ---------------- scratch (device globals; no allocation allowed) ----------------
__device__ float g_qkv[ROWS_TOT * 192];   // [row][q(64) k(64) v(64)]
__device__ float g_x[ROWS_TOT * 64];      // residual after attention
__device__ int   g_nbr[ROWS_TOT * KNNk];  // per-batch-local neighbor indices
__device__ unsigned char g_mask[ROWS_TOT];

// ---------------- k0: normalize mask dtype (u8 / i32 / f32) into g_mask ----------
// Detection over first 256 bytes:
//   any byte > 1            -> float32 (1.0f = 00 00 80 3F; i32/u8 bools only have 0/1 bytes)
//   else nonzero off-word   -> packed u8 bools
//   else                    -> int32
__global__ void k0_mask(const void* mp) {
    __shared__ int mode;
    const unsigned char* u = (const unsigned char*)mp;
    if (threadIdx.x == 0) {
        bool anyHigh = false, anyOff = false;
        for (int i = 0; i < 256; ++i) {
            unsigned char b = u[i];
            if (b > 1) anyHigh = true;
            if ((i & 3) != 0 && b != 0) anyOff = true;
        }
        mode = anyHigh ? 2 : (anyOff ? 0 : 1);
    }
    __syncthreads();
    int i = blockIdx.x * blockDim.x + threadIdx.x;
    unsigned char v;
    if (mode == 0)      v = (u[i] != 0);
    else if (mode == 1) v = (((const int*)mp)[i] != 0);
    else                v = (((const float*)mp)[i] != 0.0f);
    g_mask[i] = v;
}

// ---------------- k1: LN1 + QKV GEMM (32 rows / block) ----------------
__global__ void k1_ln_qkv(const float* __restrict__ x,
                          const float* __restrict__ g1, const float* __restrict__ b1,
                          const float* __restrict__ wq, const float* __restrict__ bq) {
    extern __shared__ float sm1[];
    float* ws  = sm1;            // 12288 = 64*192
    float* bs  = ws + 12288;     // 192
    float* xsT = bs + 192;       // 64 * 36 (transposed x-hat, pitch 36)
    int tid = threadIdx.x;
    int rowBase = blockIdx.x * 32;

    for (int i = tid; i < 12288; i += 256) ws[i] = wq[i];
    if (tid < 192) bs[tid] = bq[tid];

    int w = tid >> 5, lane = tid & 31;
#pragma unroll
    for (int rr = 0; rr < 4; ++rr) {
        int r = w * 4 + rr;
        const float* xr = x + (size_t)(rowBase + r) * 64;
        float a0 = xr[lane], a1 = xr[lane + 32];
        float s = a0 + a1, ss = a0 * a0 + a1 * a1;
#pragma unroll
        for (int o = 16; o; o >>= 1) {
            s  += __shfl_xor_sync(0xffffffffu, s, o);
            ss += __shfl_xor_sync(0xffffffffu, ss, o);
        }
        float m   = s * (1.f / 64.f);
        float var = fmaxf(ss * (1.f / 64.f) - m * m, 0.f);
        float inv = rsqrtf(var + 1e-5f);
        xsT[lane * 36 + r]        = (a0 - m) * inv * __ldg(&g1[lane])      + __ldg(&b1[lane]);
        xsT[(lane + 32) * 36 + r] = (a1 - m) * inv * __ldg(&g1[lane + 32]) + __ldg(&b1[lane + 32]);
    }
    __syncthreads();

    if (tid < 192) {
        int c = tid;
#pragma unroll
        for (int g = 0; g < 4; ++g) {
            float bb = bs[c];
            float acc[8];
#pragma unroll
            for (int i = 0; i < 8; ++i) acc[i] = bb;
#pragma unroll 4
            for (int k = 0; k < 64; ++k) {
                float wv  = ws[k * 192 + c];
                float4 xa = *(const float4*)&xsT[k * 36 + g * 8];
                float4 xb = *(const float4*)&xsT[k * 36 + g * 8 + 4];
                acc[0] = fmaf(xa.x, wv, acc[0]);
                acc[1] = fmaf(xa.y, wv, acc[1]);
                acc[2] = fmaf(xa.z, wv, acc[2]);
                acc[3] = fmaf(xa.w, wv, acc[3]);
                acc[4] = fmaf(xb.x, wv, acc[4]);
                acc[5] = fmaf(xb.y, wv, acc[5]);
                acc[6] = fmaf(xb.z, wv, acc[6]);
                acc[7] = fmaf(xb.w, wv, acc[7]);
            }
#pragma unroll
            for (int i = 0; i < 8; ++i)
                g_qkv[(size_t)(rowBase + g * 8 + i) * 192 + c] = acc[i];
        }
    }
}

// ---------------- k2: brute-force KNN, thread-per-query ----------------
// d2' = |c|^2 - 2 q.c  (constant |q|^2 offset preserves ordering & ties).
__global__ void k2_knn(const float* __restrict__ coords) {
    extern __shared__ float4 c4[];   // 4096 points: (cx,cy,cz,|c|^2), masked -> cc=3e12
    int b = blockIdx.y;
    int tid = threadIdx.x;           // 128 threads
    const float* cb = coords + (size_t)b * Nn * 3;

    for (int j = tid; j < Nn; j += 128) {
        float cx = cb[j * 3 + 0], cy = cb[j * 3 + 1], cz = cb[j * 3 + 2];
        float cc = cx * cx + cy * cy + cz * cz;
        if (!g_mask[b * Nn + j]) { cx = 0.f; cy = 0.f; cz = 0.f; cc = 3.0e12f; }
        c4[j] = make_float4(cx, cy, cz, cc);
    }
    __syncthreads();

    int q = blockIdx.x * 128 + tid;
    float qx = cb[q * 3 + 0], qy = cb[q * 3 + 1], qz = cb[q * 3 + 2];
    float nx = -2.f * qx, ny = -2.f * qy, nz = -2.f * qz;

    float d[KNNk]; int id[KNNk];
#pragma unroll
    for (int i = 0; i < KNNk; ++i) { d[i] = 3.4e38f; id[i] = 0; }

#pragma unroll 4
    for (int j = 0; j < Nn; ++j) {
        float4 c = c4[j];
        float dd = fmaf(nx, c.x, c.w);
        dd = fmaf(ny, c.y, dd);
        dd = fmaf(nz, c.z, dd);
        if (dd < d[KNNk - 1]) {   // strict <: ties keep earlier index (matches top_k)
            float dv = dd; int iv = j;
#pragma unroll
            for (int s = 0; s < KNNk; ++s) {
                if (dv < d[s]) {
                    float td = d[s]; int ti = id[s];
                    d[s] = dv; id[s] = iv; dv = td; iv = ti;
                }
            }
        }
    }
    int* o = &g_nbr[(size_t)(b * Nn + q) * KNNk];
#pragma unroll
    for (int i = 0; i < KNNk; ++i) o[i] = id[i];
}

// ---------------- k3: attention (score, top-4, softmax, PV, proj, residual) ------
__global__ void k3_attn(const float* __restrict__ inputs,
                        const float* __restrict__ wproj, const float* __restrict__ bproj) {
    __shared__ float wp[4096];
    __shared__ float bp[64];
    __shared__ __align__(16) float qs[8][64];
    __shared__ float sc[8][40];
    __shared__ float swt[8][16];
    __shared__ int   sjg[8][16];
    __shared__ int   snb[8][KNNk];
    __shared__ float ovec[8][64];

    int tid = threadIdx.x, w = tid >> 5, lane = tid & 31;
    for (int i = tid; i < 4096; i += 256) wp[i] = wproj[i];
    if (tid < 64) bp[tid] = bproj[tid];
    __syncthreads();

    int row  = blockIdx.x * 8 + w;          // global row [0, 16384)
    int base = row & ~(Nn - 1);             // batch base row

    const float* qr = &g_qkv[(size_t)row * 192];
    qs[w][lane]      = qr[lane];
    qs[w][lane + 32] = qr[lane + 32];
    if (lane < KNNk) snb[w][lane] = g_nbr[(size_t)row * KNNk + lane];
    __syncwarp();

    // scores: 40 (head, neighbor) pairs
    for (int t = lane; t < Hh * KNNk; t += 32) {
        int h = t / KNNk, j = t - h * KNNk;
        int jl = snb[w][j];
        const float* kp = &g_qkv[(size_t)(base + jl) * 192 + 64 + h * DH];
        const float* qp = &qs[w][h * DH];
        float4 k0 = *(const float4*)(kp);
        float4 k1 = *(const float4*)(kp + 4);
        float4 k2 = *(const float4*)(kp + 8);
        float4 k3 = *(const float4*)(kp + 12);
        float4 q0 = *(const float4*)(qp);
        float4 q1 = *(const float4*)(qp + 4);
        float4 q2 = *(const float4*)(qp + 8);
        float4 q3 = *(const float4*)(qp + 12);
        float acc = k0.x * q0.x + k0.y * q0.y + k0.z * q0.z + k0.w * q0.w
                  + k1.x * q1.x + k1.y * q1.y + k1.z * q1.z + k1.w * q1.w
                  + k2.x * q2.x + k2.y * q2.y + k2.z * q2.z + k2.w * q2.w
                  + k3.x * q3.x + k3.y * q3.y + k3.z * q3.z + k3.w * q3.w;
        float s = acc * 0.25f;              // 1/sqrt(16)
        if (!g_mask[base + jl]) s -= 1e9f;
        sc[w][t] = s;
    }
    __syncwarp();

    // top-4 + softmax per head (lanes 0..3)
    if (lane < Hh) {
        int h = lane;
        float bv0 = -3.4e38f, bv1 = -3.4e38f, bv2 = -3.4e38f, bv3 = -3.4e38f;
        int   bi0 = 0, bi1 = 0, bi2 = 0, bi3 = 0;
#pragma unroll
        for (int j = 0; j < KNNk; ++j) {
            float v = sc[w][h * KNNk + j]; int vi = j;
            if (v > bv0) { float t = bv0; int ti = bi0; bv0 = v; bi0 = vi; v = t; vi = ti; }
            if (v > bv1) { float t = bv1; int ti = bi1; bv1 = v; bi1 = vi; v = t; vi = ti; }
            if (v > bv2) { float t = bv2; int ti = bi2; bv2 = v; bi2 = vi; v = t; vi = ti; }
            if (v > bv3) { float t = bv3; int ti = bi3; bv3 = v; bi3 = vi; v = t; vi = ti; }
        }
        float e1 = __expf(bv1 - bv0), e2 = __expf(bv2 - bv0), e3 = __expf(bv3 - bv0);
        float inv = 1.f / (1.f + e1 + e2 + e3);
        swt[w][h * 4 + 0] = inv;
        swt[w][h * 4 + 1] = e1 * inv;
        swt[w][h * 4 + 2] = e2 * inv;
        swt[w][h * 4 + 3] = e3 * inv;
        sjg[w][h * 4 + 0] = base + snb[w][bi0];
        sjg[w][h * 4 + 1] = base + snb[w][bi1];
        sjg[w][h * 4 + 2] = base + snb[w][bi2];
        sjg[w][h * 4 + 3] = base + snb[w][bi3];
    }
    __syncwarp();

    // o = sum_s w_s * v_sel  (2 channels per lane)
    {
        int c0 = lane, c1 = lane + 32;
        int h0 = c0 >> 4, h1 = c1 >> 4;
        float a0 = 0.f, a1 = 0.f;
#pragma unroll
        for (int s = 0; s < KSk; ++s) {
            a0 += swt[w][h0 * 4 + s] * g_qkv[(size_t)sjg[w][h0 * 4 + s] * 192 + 128 + c0];
            a1 += swt[w][h1 * 4 + s] * g_qkv[(size_t)sjg[w][h1 * 4 + s] * 192 + 128 + c1];
        }
        ovec[w][c0] = a0; ovec[w][c1] = a1;
    }
    __syncwarp();

    // proj + mask + residual -> g_x
    {
        float acc0 = bp[lane], acc1 = bp[lane + 32];
#pragma unroll 4
        for (int k = 0; k < 64; ++k) {
            float ov = ovec[w][k];
            acc0 = fmaf(ov, wp[k * 64 + lane], acc0);
            acc1 = fmaf(ov, wp[k * 64 + lane + 32], acc1);
        }
        float half0 = g_mask[row] ? 0.5f : 0.f;
        const float* ir = inputs + (size_t)row * 64;
        g_x[(size_t)row * 64 + lane]      = fmaf(half0, acc0, ir[lane]);
        g_x[(size_t)row * 64 + lane + 32] = fmaf(half0, acc1, ir[lane + 32]);
    }
}

// ---------------- k4: LN2 + MLP (64->256 gelu 256->64) + residual ----------------
__global__ void k4_mlp(const float* __restrict__ g2, const float* __restrict__ b2,
                       const float* __restrict__ w1, const float* __restrict__ b1,
                       const float* __restrict__ w2, const float* __restrict__ b2o,
                       float* __restrict__ out) {
    extern __shared__ float sm4[];
    float* w1s = sm4;             // 16384 = 64*256
    float* w2s = w1s + 16384;     // 16384 = 256*64
    float* b1s = w2s + 16384;     // 256
    float* xsT = b1s + 256;       // 64 * 36
    float* h1T = xsT + 2304;      // 256 * 36
    int tid = threadIdx.x;
    int rowBase = blockIdx.x * 32;

    for (int i = tid; i < 16384; i += 256) { w1s[i] = w1[i]; w2s[i] = w2[i]; }
    b1s[tid] = b1[tid];

    int w = tid >> 5, lane = tid & 31;
#pragma unroll
    for (int rr = 0; rr < 4; ++rr) {
        int r = w * 4 + rr;
        const float* xr = &g_x[(size_t)(rowBase + r) * 64];
        float a0 = xr[lane], a1 = xr[lane + 32];
        float s = a0 + a1, ss = a0 * a0 + a1 * a1;
#pragma unroll
        for (int o = 16; o; o >>= 1) {
            s  += __shfl_xor_sync(0xffffffffu, s, o);
            ss += __shfl_xor_sync(0xffffffffu, ss, o);
        }
        float m   = s * (1.f / 64.f);
        float var = fmaxf(ss * (1.f / 64.f) - m * m, 0.f);
        float inv = rsqrtf(var + 1e-5f);
        xsT[lane * 36 + r]        = (a0 - m) * inv * __ldg(&g2[lane])      + __ldg(&b2[lane]);
        xsT[(lane + 32) * 36 + r] = (a1 - m) * inv * __ldg(&g2[lane + 32]) + __ldg(&b2[lane + 32]);
    }
    __syncthreads();

    // h1[m][r] = gelu(xhat @ w1 + b1), thread = column m, 4 groups of 8 rows
    {
        int mcol = tid;
#pragma unroll
        for (int g = 0; g < 4; ++g) {
            float bb = b1s[mcol];
            float acc[8];
#pragma unroll
            for (int i = 0; i < 8; ++i) acc[i] = bb;
#pragma unroll 4
            for (int k = 0; k < 64; ++k) {
                float wv  = w1s[k * 256 + mcol];
                float4 xa = *(const float4*)&xsT[k * 36 + g * 8];
                float4 xb = *(const float4*)&xsT[k * 36 + g * 8 + 4];
                acc[0] = fmaf(xa.x, wv, acc[0]);
                acc[1] = fmaf(xa.y, wv, acc[1]);
                acc[2] = fmaf(xa.z, wv, acc[2]);
                acc[3] = fmaf(xa.w, wv, acc[3]);
                acc[4] = fmaf(xb.x, wv, acc[4]);
                acc[5] = fmaf(xb.y, wv, acc[5]);
                acc[6] = fmaf(xb.z, wv, acc[6]);
                acc[7] = fmaf(xb.w, wv, acc[7]);
            }
#pragma unroll
            for (int i = 0; i < 8; ++i) {
                float xv = acc[i];
                float u = 0.7978845608028654f * (xv + 0.044715f * xv * xv * xv);
                float th;
                asm("tanh.approx.f32 %0, %1;" : "=f"(th) : "f"(u));
                h1T[mcol * 36 + g * 8 + i] = 0.5f * xv * (1.f + th);
            }
        }
    }
    __syncthreads();

    // h2[r][c] = h1 @ w2 + b2; out = 0.5*h2 + x
    {
        int c = tid & 63, rg = tid >> 6;   // 4 row-groups of 8
        float bb = __ldg(&b2o[c]);
        float acc[8];
#pragma unroll
        for (int i = 0; i < 8; ++i) acc[i] = bb;
#pragma unroll 2
        for (int k = 0; k < 256; ++k) {
            float wv  = w2s[k * 64 + c];
            float4 ha = *(const float4*)&h1T[k * 36 + rg * 8];
            float4 hb = *(const float4*)&h1T[k * 36 + rg * 8 + 4];
            acc[0] = fmaf(ha.x, wv, acc[0]);
            acc[1] = fmaf(ha.y, wv, acc[1]);
            acc[2] = fmaf(ha.z, wv, acc[2]);
            acc[3] = fmaf(ha.w, wv, acc[3]);
            acc[4] = fmaf(hb.x, wv, acc[4]);
            acc[5] = fmaf(hb.y, wv, acc[5]);
            acc[6] = fmaf(hb.z, wv, acc[6]);
            acc[7] = fmaf(hb.w, wv, acc[7]);
        }
#pragma unroll
        for (int i = 0; i < 8; ++i) {
            size_t row = (size_t)rowBase + rg * 8 + i;
            out[row * 64 + c] = fmaf(0.5f, acc[i], g_x[row * 64 + c]);
        }
    }
}

// ---------------- launch ----------------
extern "C" void kernel_launch(void* const* d_in, const int* in_sizes, int n_in,
                              void* d_out, int out_size) {
    (void)in_sizes; (void)n_in; (void)out_size;
    const float* inputs = (const float*)d_in[0];
    const float* coords = (const float*)d_in[1];
    const void*  maskp  = d_in[2];
    const float* ln1g   = (const float*)d_in[3];
    const float* ln1b   = (const float*)d_in[4];
    const float* ln2g   = (const float*)d_in[5];
    const float* ln2b   = (const float*)d_in[6];
    const float* wqkv   = (const float*)d_in[7];
    const float* bqkv   = (const float*)d_in[8];
    const float* wproj  = (const float*)d_in[9];
    const float* bproj  = (const float*)d_in[10];
    const float* w1     = (const float*)d_in[11];
    const float* b1     = (const float*)d_in[12];
    const float* w2     = (const float*)d_in[13];
    const float* b2     = (const float*)d_in[14];
    float* out = (float*)d_out;

    cudaFuncSetAttribute(k1_ln_qkv, cudaFuncAttributeMaxDynamicSharedMemorySize, 59136);
    cudaFuncSetAttribute(k2_knn,    cudaFuncAttributeMaxDynamicSharedMemorySize, 65536);
    cudaFuncSetAttribute(k4_mlp,    cudaFuncAttributeMaxDynamicSharedMemorySize, 178176);

    k0_mask<<<64, 256>>>(maskp);
    k1_ln_qkv<<<512, 256, 59136>>>(inputs, ln1g, ln1b, wqkv, bqkv);
    k2_knn<<<dim3(32, 4), 128, 65536>>>(coords);
    k3_attn<<<2048, 256>>>(inputs, wproj, bproj);
    k4_mlp<<<512, 256, 178176>>>(ln2g, ln2b, w1, b1, w2, b2, out);
}

// round 9
// speedup vs baseline: 1.3048x; 1.3048x over previous
#include <cuda_runtime.h>
#include <cuda_bf16.h>
#include <cstdint>

#define Bb 4
#define Nn 4096
#define Cc 64
#define Hh 4
#define DH 16
#define KNNk 10
#define KSk 4
#define Mm 256
#define ROWS_TOT (Bb * Nn)

// ---------------- scratch (device globals; no allocation allowed) ----------------
__device__ float g_qkv[ROWS_TOT * 192];   // [row][q(64) k(64) v(64)]
__device__ float g_x[ROWS_TOT * 64];      // residual after attention
__device__ int   g_nbr[ROWS_TOT * KNNk];  // per-batch-local neighbor indices
__device__ unsigned char g_mask[ROWS_TOT];
__device__ float4 g_bpts[Bb * Nn];        // binned unmasked points (x,y,z,idx-bits)
__device__ int2   g_cellrange[Bb * 4096]; // per-cell (start, count) into g_bpts
__device__ int    g_qord[Bb * Nn];        // all queries sorted by cell (locality)

// ---------------- k0: normalize mask dtype (u8 / i32 / f32) into g_mask ----------
__global__ void k0_mask(const void* mp) {
    __shared__ int mode;
    const unsigned char* u = (const unsigned char*)mp;
    if (threadIdx.x == 0) {
        bool anyHigh = false, anyOff = false;
        for (int i = 0; i < 256; ++i) {
            unsigned char b = u[i];
            if (b > 1) anyHigh = true;
            if ((i & 3) != 0 && b != 0) anyOff = true;
        }
        mode = anyHigh ? 2 : (anyOff ? 0 : 1);
    }
    __syncthreads();
    int i = blockIdx.x * blockDim.x + threadIdx.x;
    unsigned char v;
    if (mode == 0)      v = (u[i] != 0);
    else if (mode == 1) v = (((const int*)mp)[i] != 0);
    else                v = (((const float*)mp)[i] != 0.0f);
    g_mask[i] = v;
}

// ---------------- k1: LN1 + QKV GEMM (32 rows / block) ----------------
__global__ void k1_ln_qkv(const float* __restrict__ x,
                          const float* __restrict__ g1, const float* __restrict__ b1,
                          const float* __restrict__ wq, const float* __restrict__ bq) {
    extern __shared__ float sm1[];
    float* ws  = sm1;            // 12288 = 64*192
    float* bs  = ws + 12288;     // 192
    float* xsT = bs + 192;       // 64 * 36 (transposed x-hat, pitch 36)
    int tid = threadIdx.x;
    int rowBase = blockIdx.x * 32;

    for (int i = tid; i < 12288; i += 256) ws[i] = wq[i];
    if (tid < 192) bs[tid] = bq[tid];

    int w = tid >> 5, lane = tid & 31;
#pragma unroll
    for (int rr = 0; rr < 4; ++rr) {
        int r = w * 4 + rr;
        const float* xr = x + (size_t)(rowBase + r) * 64;
        float a0 = xr[lane], a1 = xr[lane + 32];
        float s = a0 + a1, ss = a0 * a0 + a1 * a1;
#pragma unroll
        for (int o = 16; o; o >>= 1) {
            s  += __shfl_xor_sync(0xffffffffu, s, o);
            ss += __shfl_xor_sync(0xffffffffu, ss, o);
        }
        float m   = s * (1.f / 64.f);
        float var = fmaxf(ss * (1.f / 64.f) - m * m, 0.f);
        float inv = rsqrtf(var + 1e-5f);
        xsT[lane * 36 + r]        = (a0 - m) * inv * __ldg(&g1[lane])      + __ldg(&b1[lane]);
        xsT[(lane + 32) * 36 + r] = (a1 - m) * inv * __ldg(&g1[lane + 32]) + __ldg(&b1[lane + 32]);
    }
    __syncthreads();

    if (tid < 192) {
        int c = tid;
#pragma unroll
        for (int g = 0; g < 4; ++g) {
            float bb = bs[c];
            float acc[8];
#pragma unroll
            for (int i = 0; i < 8; ++i) acc[i] = bb;
#pragma unroll 4
            for (int k = 0; k < 64; ++k) {
                float wv  = ws[k * 192 + c];
                float4 xa = *(const float4*)&xsT[k * 36 + g * 8];
                float4 xb = *(const float4*)&xsT[k * 36 + g * 8 + 4];
                acc[0] = fmaf(xa.x, wv, acc[0]);
                acc[1] = fmaf(xa.y, wv, acc[1]);
                acc[2] = fmaf(xa.z, wv, acc[2]);
                acc[3] = fmaf(xa.w, wv, acc[3]);
                acc[4] = fmaf(xb.x, wv, acc[4]);
                acc[5] = fmaf(xb.y, wv, acc[5]);
                acc[6] = fmaf(xb.z, wv, acc[6]);
                acc[7] = fmaf(xb.w, wv, acc[7]);
            }
#pragma unroll
            for (int i = 0; i < 8; ++i)
                g_qkv[(size_t)(rowBase + g * 8 + i) * 192 + c] = acc[i];
        }
    }
}

// ---------------- k2a: bin points into 16^3 grid (counting sort) -----------------
// pass 0: unmasked points -> g_bpts + g_cellrange.  pass 1: all points -> g_qord.
__global__ void k2a_bins(const float* __restrict__ coords) {
    __shared__ unsigned int cnts[4096];
    __shared__ unsigned int starts[4096];
    __shared__ unsigned int wsum[32];
    int b = blockIdx.x, tid = threadIdx.x;           // 1024 threads
    const float* cb = coords + (size_t)b * Nn * 3;
    int lane = tid & 31, wid = tid >> 5;

    for (int pass = 0; pass < 2; ++pass) {
        for (int i = tid; i < 4096; i += 1024) cnts[i] = 0;
        __syncthreads();
        for (int i = tid; i < Nn; i += 1024) {
            if (pass == 0 && !g_mask[b * Nn + i]) continue;
            float x = cb[i * 3], y = cb[i * 3 + 1], z = cb[i * 3 + 2];
            int cx = min(15, (int)x), cy = min(15, (int)y), cz = min(15, (int)z);
            atomicAdd(&cnts[(cz * 16 + cy) * 16 + cx], 1u);
        }
        __syncthreads();
        // exclusive scan of 4096 counts (4 per thread)
        unsigned v0 = cnts[tid * 4], v1 = cnts[tid * 4 + 1],
                 v2 = cnts[tid * 4 + 2], v3 = cnts[tid * 4 + 3];
        unsigned tot = v0 + v1 + v2 + v3;
        unsigned inc = tot;
#pragma unroll
        for (int o = 1; o < 32; o <<= 1) {
            unsigned n = __shfl_up_sync(0xffffffffu, inc, o);
            if (lane >= o) inc += n;
        }
        if (lane == 31) wsum[wid] = inc;
        __syncthreads();
        if (wid == 0) {
            unsigned t = wsum[lane];
            unsigned i2 = t;
#pragma unroll
            for (int o = 1; o < 32; o <<= 1) {
                unsigned n = __shfl_up_sync(0xffffffffu, i2, o);
                if (lane >= o) i2 += n;
            }
            wsum[lane] = i2 - t;
        }
        __syncthreads();
        unsigned base = wsum[wid] + (inc - tot);
        unsigned s0 = base, s1 = base + v0, s2 = s1 + v1, s3 = s2 + v2;
        starts[tid * 4] = s0; starts[tid * 4 + 1] = s1;
        starts[tid * 4 + 2] = s2; starts[tid * 4 + 3] = s3;
        if (pass == 0) {
            g_cellrange[b * 4096 + tid * 4 + 0] = make_int2((int)s0, (int)v0);
            g_cellrange[b * 4096 + tid * 4 + 1] = make_int2((int)s1, (int)v1);
            g_cellrange[b * 4096 + tid * 4 + 2] = make_int2((int)s2, (int)v2);
            g_cellrange[b * 4096 + tid * 4 + 3] = make_int2((int)s3, (int)v3);
        }
        __syncthreads();
        for (int i = tid; i < Nn; i += 1024) {
            if (pass == 0 && !g_mask[b * Nn + i]) continue;
            float x = cb[i * 3], y = cb[i * 3 + 1], z = cb[i * 3 + 2];
            int cx = min(15, (int)x), cy = min(15, (int)y), cz = min(15, (int)z);
            unsigned pos = atomicAdd(&starts[(cz * 16 + cy) * 16 + cx], 1u);
            if (pass == 0) g_bpts[b * Nn + pos] = make_float4(x, y, z, __int_as_float(i));
            else           g_qord[b * Nn + pos] = i;
        }
        __syncthreads();
    }
}

// ---------------- k2b: exact KNN via expanding shells over the grid --------------
// d' = |c|^2 - 2 q.c (shifted by -|q|^2; ordering preserved, same math as before).
// Shell bound: any point in a cell at Chebyshev ring s is >= (s-1) away (cell=1.0),
// so stop once (s-1)^2 > d'[9] + |q|^2 (true 10th-best squared distance).
__global__ void k2b_knn(const float* __restrict__ coords) {
    int t = blockIdx.x * 128 + threadIdx.x;          // bin-ordered query slot
    int b = blockIdx.y;
    int q = g_qord[b * Nn + t];
    const float* cb = coords + (size_t)b * Nn * 3;
    float qx = cb[q * 3], qy = cb[q * 3 + 1], qz = cb[q * 3 + 2];
    float qq = fmaf(qx, qx, fmaf(qy, qy, qz * qz));
    float nx = -2.f * qx, ny = -2.f * qy, nz = -2.f * qz;
    int qcx = min(15, (int)qx), qcy = min(15, (int)qy), qcz = min(15, (int)qz);

    const float4* bp = &g_bpts[b * Nn];
    const int2*   cr = &g_cellrange[b * 4096];

    float d[KNNk]; int id[KNNk];
#pragma unroll
    for (int i = 0; i < KNNk; ++i) { d[i] = 3.4e38f; id[i] = 0; }

    for (int s = 0; s < 16; ++s) {
        bool active = (s < 2) || ((float)((s - 1) * (s - 1)) <= d[KNNk - 1] + qq);
        if (!__any_sync(0xffffffffu, active)) break;
        if (active) {
            for (int dz = -s; dz <= s; ++dz) {
                int z = qcz + dz;
                if ((unsigned)z > 15u) continue;
                bool ez = (dz == -s) | (dz == s);
                for (int dy = -s; dy <= s; ++dy) {
                    int y = qcy + dy;
                    if ((unsigned)y > 15u) continue;
                    bool ey = (dy == -s) | (dy == s);
                    int step = (ez | ey) ? 1 : (s > 0 ? 2 * s : 1);
                    for (int dx = -s; dx <= s; dx += step) {
                        int xx = qcx + dx;
                        if ((unsigned)xx > 15u) continue;
                        int2 rg = __ldg(&cr[(z * 16 + y) * 16 + xx]);
                        int pe = rg.x + rg.y;
                        for (int p = rg.x; p < pe; ++p) {
                            float4 c = __ldg(&bp[p]);
                            float cc = fmaf(c.x, c.x, fmaf(c.y, c.y, c.z * c.z));
                            float dd = fmaf(nx, c.x, fmaf(ny, c.y, fmaf(nz, c.z, cc)));
                            if (dd < d[KNNk - 1]) {
                                // branchless sorted insert (single divergence region)
                                float cv = dd; int ci = __float_as_int(c.w);
#pragma unroll
                                for (int k = 0; k < KNNk; ++k) {
                                    bool pr = cv < d[k];
                                    float tf = d[k]; int ti = id[k];
                                    d[k]  = pr ? cv : tf;
                                    id[k] = pr ? ci : ti;
                                    cv    = pr ? tf : cv;
                                    ci    = pr ? ti : ci;
                                }
                            }
                        }
                    }
                }
            }
        }
    }
    int* o = &g_nbr[(size_t)(b * Nn + q) * KNNk];
#pragma unroll
    for (int i = 0; i < KNNk; ++i) o[i] = id[i];
}

// ---------------- k3: attention (64 rows / block, warp loops 8 rows) -------------
__global__ void k3_attn(const float* __restrict__ inputs,
                        const float* __restrict__ wproj, const float* __restrict__ bproj) {
    __shared__ float wp[4096];
    __shared__ float bp[64];
    __shared__ __align__(16) float qs[8][64];
    __shared__ float sc[8][40];
    __shared__ float swt[8][16];
    __shared__ int   sjg[8][16];
    __shared__ int   snb[8][KNNk];
    __shared__ float ovec[8][64];

    int tid = threadIdx.x, w = tid >> 5, lane = tid & 31;
    for (int i = tid; i < 4096; i += 256) wp[i] = wproj[i];
    if (tid < 64) bp[tid] = bproj[tid];
    __syncthreads();

    for (int r8 = 0; r8 < 8; ++r8) {
        int row  = blockIdx.x * 64 + w * 8 + r8;
        int base = row & ~(Nn - 1);

        const float* qr = &g_qkv[(size_t)row * 192];
        qs[w][lane]      = qr[lane];
        qs[w][lane + 32] = qr[lane + 32];
        if (lane < KNNk) snb[w][lane] = g_nbr[(size_t)row * KNNk + lane];
        __syncwarp();

        for (int t = lane; t < Hh * KNNk; t += 32) {
            int h = t / KNNk, j = t - h * KNNk;
            int jl = snb[w][j];
            const float* kp = &g_qkv[(size_t)(base + jl) * 192 + 64 + h * DH];
            const float* qp = &qs[w][h * DH];
            float4 k0 = *(const float4*)(kp);
            float4 k1 = *(const float4*)(kp + 4);
            float4 k2 = *(const float4*)(kp + 8);
            float4 k3 = *(const float4*)(kp + 12);
            float4 q0 = *(const float4*)(qp);
            float4 q1 = *(const float4*)(qp + 4);
            float4 q2 = *(const float4*)(qp + 8);
            float4 q3 = *(const float4*)(qp + 12);
            float acc = k0.x * q0.x + k0.y * q0.y + k0.z * q0.z + k0.w * q0.w
                      + k1.x * q1.x + k1.y * q1.y + k1.z * q1.z + k1.w * q1.w
                      + k2.x * q2.x + k2.y * q2.y + k2.z * q2.z + k2.w * q2.w
                      + k3.x * q3.x + k3.y * q3.y + k3.z * q3.z + k3.w * q3.w;
            float s = acc * 0.25f;
            if (!g_mask[base + jl]) s -= 1e9f;
            sc[w][t] = s;
        }
        __syncwarp();

        if (lane < Hh) {
            int h = lane;
            float bv0 = -3.4e38f, bv1 = -3.4e38f, bv2 = -3.4e38f, bv3 = -3.4e38f;
            int   bi0 = 0, bi1 = 0, bi2 = 0, bi3 = 0;
#pragma unroll
            for (int j = 0; j < KNNk; ++j) {
                float v = sc[w][h * KNNk + j]; int vi = j;
                if (v > bv0) { float t0 = bv0; int ti = bi0; bv0 = v; bi0 = vi; v = t0; vi = ti; }
                if (v > bv1) { float t0 = bv1; int ti = bi1; bv1 = v; bi1 = vi; v = t0; vi = ti; }
                if (v > bv2) { float t0 = bv2; int ti = bi2; bv2 = v; bi2 = vi; v = t0; vi = ti; }
                if (v > bv3) { float t0 = bv3; int ti = bi3; bv3 = v; bi3 = vi; v = t0; vi = ti; }
            }
            float e1 = __expf(bv1 - bv0), e2 = __expf(bv2 - bv0), e3 = __expf(bv3 - bv0);
            float inv = 1.f / (1.f + e1 + e2 + e3);
            swt[w][h * 4 + 0] = inv;
            swt[w][h * 4 + 1] = e1 * inv;
            swt[w][h * 4 + 2] = e2 * inv;
            swt[w][h * 4 + 3] = e3 * inv;
            sjg[w][h * 4 + 0] = base + snb[w][bi0];
            sjg[w][h * 4 + 1] = base + snb[w][bi1];
            sjg[w][h * 4 + 2] = base + snb[w][bi2];
            sjg[w][h * 4 + 3] = base + snb[w][bi3];
        }
        __syncwarp();

        {
            int c0 = lane, c1 = lane + 32;
            int h0 = c0 >> 4, h1 = c1 >> 4;
            float a0 = 0.f, a1 = 0.f;
#pragma unroll
            for (int s = 0; s < KSk; ++s) {
                a0 += swt[w][h0 * 4 + s] * g_qkv[(size_t)sjg[w][h0 * 4 + s] * 192 + 128 + c0];
                a1 += swt[w][h1 * 4 + s] * g_qkv[(size_t)sjg[w][h1 * 4 + s] * 192 + 128 + c1];
            }
            ovec[w][c0] = a0; ovec[w][c1] = a1;
        }
        __syncwarp();

        {
            float acc0 = bp[lane], acc1 = bp[lane + 32];
#pragma unroll 4
            for (int k = 0; k < 64; ++k) {
                float ov = ovec[w][k];
                acc0 = fmaf(ov, wp[k * 64 + lane], acc0);
                acc1 = fmaf(ov, wp[k * 64 + lane + 32], acc1);
            }
            float half0 = g_mask[row] ? 0.5f : 0.f;
            const float* ir = inputs + (size_t)row * 64;
            g_x[(size_t)row * 64 + lane]      = fmaf(half0, acc0, ir[lane]);
            g_x[(size_t)row * 64 + lane + 32] = fmaf(half0, acc1, ir[lane + 32]);
        }
        __syncwarp();
    }
}

// ---------------- k4: LN2 + MLP (64 rows / block, 512 threads) -------------------
__global__ void k4_mlp(const float* __restrict__ g2, const float* __restrict__ b2,
                       const float* __restrict__ w1, const float* __restrict__ b1,
                       const float* __restrict__ w2, const float* __restrict__ b2o,
                       float* __restrict__ out) {
    extern __shared__ float sm4[];
    float* w1s = sm4;             // 16384 = 64*256
    float* w2s = w1s + 16384;     // 16384 = 256*64
    float* b1s = w2s + 16384;     // 256
    float* xsT = b1s + 256;       // 64 * 68
    float* h1T = xsT + 4352;      // 256 * 68
    int tid = threadIdx.x;        // 512 threads
    int rowBase = blockIdx.x * 64;

    for (int i = tid; i < 16384; i += 512) { w1s[i] = w1[i]; w2s[i] = w2[i]; }
    if (tid < 256) b1s[tid] = b1[tid];

    int w = tid >> 5, lane = tid & 31;   // 16 warps x 4 rows = 64 rows
#pragma unroll
    for (int rr = 0; rr < 4; ++rr) {
        int r = w * 4 + rr;
        const float* xr = &g_x[(size_t)(rowBase + r) * 64];
        float a0 = xr[lane], a1 = xr[lane + 32];
        float s = a0 + a1, ss = a0 * a0 + a1 * a1;
#pragma unroll
        for (int o = 16; o; o >>= 1) {
            s  += __shfl_xor_sync(0xffffffffu, s, o);
            ss += __shfl_xor_sync(0xffffffffu, ss, o);
        }
        float m   = s * (1.f / 64.f);
        float var = fmaxf(ss * (1.f / 64.f) - m * m, 0.f);
        float inv = rsqrtf(var + 1e-5f);
        xsT[lane * 68 + r]        = (a0 - m) * inv * __ldg(&g2[lane])      + __ldg(&b2[lane]);
        xsT[(lane + 32) * 68 + r] = (a1 - m) * inv * __ldg(&g2[lane + 32]) + __ldg(&b2[lane + 32]);
    }
    __syncthreads();

    // h1[m][r] = gelu(xhat @ w1 + b1); thread = (col m, row-half), 4 groups of 8 rows
    {
        int mcol = tid & 255, half = tid >> 8;
#pragma unroll
        for (int g = 0; g < 4; ++g) {
            int r0 = half * 32 + g * 8;
            float bb = b1s[mcol];
            float acc[8];
#pragma unroll
            for (int i = 0; i < 8; ++i) acc[i] = bb;
#pragma unroll 4
            for (int k = 0; k < 64; ++k) {
                float wv  = w1s[k * 256 + mcol];
                float4 xa = *(const float4*)&xsT[k * 68 + r0];
                float4 xb = *(const float4*)&xsT[k * 68 + r0 + 4];
                acc[0] = fmaf(xa.x, wv, acc[0]);
                acc[1] = fmaf(xa.y, wv, acc[1]);
                acc[2] = fmaf(xa.z, wv, acc[2]);
                acc[3] = fmaf(xa.w, wv, acc[3]);
                acc[4] = fmaf(xb.x, wv, acc[4]);
                acc[5] = fmaf(xb.y, wv, acc[5]);
                acc[6] = fmaf(xb.z, wv, acc[6]);
                acc[7] = fmaf(xb.w, wv, acc[7]);
            }
#pragma unroll
            for (int i = 0; i < 8; ++i) {
                float xv = acc[i];
                float u = 0.7978845608028654f * (xv + 0.044715f * xv * xv * xv);
                float th;
                asm("tanh.approx.f32 %0, %1;" : "=f"(th) : "f"(u));
                h1T[mcol * 68 + r0 + i] = 0.5f * xv * (1.f + th);
            }
        }
    }
    __syncthreads();

    // h2[r][c] = h1 @ w2 + b2; out = 0.5*h2 + x
    {
        int c = tid & 63, rg = tid >> 6;   // 8 row-groups of 8
        float bb = __ldg(&b2o[c]);
        float acc[8];
#pragma unroll
        for (int i = 0; i < 8; ++i) acc[i] = bb;
#pragma unroll 2
        for (int k = 0; k < 256; ++k) {
            float wv  = w2s[k * 64 + c];
            float4 ha = *(const float4*)&h1T[k * 68 + rg * 8];
            float4 hb = *(const float4*)&h1T[k * 68 + rg * 8 + 4];
            acc[0] = fmaf(ha.x, wv, acc[0]);
            acc[1] = fmaf(ha.y, wv, acc[1]);
            acc[2] = fmaf(ha.z, wv, acc[2]);
            acc[3] = fmaf(ha.w, wv, acc[3]);
            acc[4] = fmaf(hb.x, wv, acc[4]);
            acc[5] = fmaf(hb.y, wv, acc[5]);
            acc[6] = fmaf(hb.z, wv, acc[6]);
            acc[7] = fmaf(hb.w, wv, acc[7]);
        }
#pragma unroll
        for (int i = 0; i < 8; ++i) {
            size_t row = (size_t)rowBase + rg * 8 + i;
            out[row * 64 + c] = fmaf(0.5f, acc[i], g_x[row * 64 + c]);
        }
    }
}

// ---------------- launch ----------------
extern "C" void kernel_launch(void* const* d_in, const int* in_sizes, int n_in,
                              void* d_out, int out_size) {
    (void)in_sizes; (void)n_in; (void)out_size;
    const float* inputs = (const float*)d_in[0];
    const float* coords = (const float*)d_in[1];
    const void*  maskp  = d_in[2];
    const float* ln1g   = (const float*)d_in[3];
    const float* ln1b   = (const float*)d_in[4];
    const float* ln2g   = (const float*)d_in[5];
    const float* ln2b   = (const float*)d_in[6];
    const float* wqkv   = (const float*)d_in[7];
    const float* bqkv   = (const float*)d_in[8];
    const float* wproj  = (const float*)d_in[9];
    const float* bproj  = (const float*)d_in[10];
    const float* w1     = (const float*)d_in[11];
    const float* b1     = (const float*)d_in[12];
    const float* w2     = (const float*)d_in[13];
    const float* b2     = (const float*)d_in[14];
    float* out = (float*)d_out;

    cudaFuncSetAttribute(k1_ln_qkv, cudaFuncAttributeMaxDynamicSharedMemorySize, 59136);
    cudaFuncSetAttribute(k4_mlp,    cudaFuncAttributeMaxDynamicSharedMemorySize, 219136);

    k0_mask<<<64, 256>>>(maskp);
    k2a_bins<<<4, 1024>>>(coords);
    k1_ln_qkv<<<512, 256, 59136>>>(inputs, ln1g, ln1b, wqkv, bqkv);
    k2b_knn<<<dim3(32, 4), 128>>>(coords);
    k3_attn<<<256, 256>>>(inputs, wproj, bproj);
    k4_mlp<<<256, 512, 219136>>>(ln2g, ln2b, w1, b1, w2, b2, out);
}

// round 10
// speedup vs baseline: 1.8445x; 1.4136x over previous
#include <cuda_runtime.h>
#include <cuda_bf16.h>
#include <cstdint>

#define Bb 4
#define Nn 4096
#define Cc 64
#define Hh 4
#define DH 16
#define KNNk 10
#define KSk 4
#define Mm 256
#define ROWS_TOT (Bb * Nn)

// ---------------- scratch (device globals; no allocation allowed) ----------------
__device__ float g_qkv[ROWS_TOT * 192];   // [row][q(64) k(64) v(64)]
__device__ float g_x[ROWS_TOT * 64];      // residual after attention
__device__ int   g_nbr[ROWS_TOT * KNNk];  // per-batch-local neighbor indices
__device__ unsigned char g_mask[ROWS_TOT];
__device__ float4 g_bpts[Bb * Nn];        // binned unmasked points (x,y,z,idx-bits)
__device__ int2   g_cellrange[Bb * 4096]; // per-cell (start, count) into g_bpts
__device__ int    g_qord[Bb * Nn];        // all queries sorted by cell (locality)

// ---------------- k0: normalize mask dtype (u8 / i32 / f32) into g_mask ----------
__global__ void k0_mask(const void* mp) {
    __shared__ int mode;
    const unsigned char* u = (const unsigned char*)mp;
    if (threadIdx.x == 0) {
        bool anyHigh = false, anyOff = false;
        for (int i = 0; i < 256; ++i) {
            unsigned char b = u[i];
            if (b > 1) anyHigh = true;
            if ((i & 3) != 0 && b != 0) anyOff = true;
        }
        mode = anyHigh ? 2 : (anyOff ? 0 : 1);
    }
    __syncthreads();
    int i = blockIdx.x * blockDim.x + threadIdx.x;
    unsigned char v;
    if (mode == 0)      v = (u[i] != 0);
    else if (mode == 1) v = (((const int*)mp)[i] != 0);
    else                v = (((const float*)mp)[i] != 0.0f);
    g_mask[i] = v;
}

// ---------------- k1: LN1 + QKV GEMM (32 rows / block) ----------------
__global__ void k1_ln_qkv(const float* __restrict__ x,
                          const float* __restrict__ g1, const float* __restrict__ b1,
                          const float* __restrict__ wq, const float* __restrict__ bq) {
    extern __shared__ float sm1[];
    float* ws  = sm1;            // 12288 = 64*192
    float* bs  = ws + 12288;     // 192
    float* xsT = bs + 192;       // 64 * 36 (transposed x-hat, pitch 36)
    int tid = threadIdx.x;
    int rowBase = blockIdx.x * 32;

    for (int i = tid; i < 12288; i += 256) ws[i] = wq[i];
    if (tid < 192) bs[tid] = bq[tid];

    int w = tid >> 5, lane = tid & 31;
#pragma unroll
    for (int rr = 0; rr < 4; ++rr) {
        int r = w * 4 + rr;
        const float* xr = x + (size_t)(rowBase + r) * 64;
        float a0 = xr[lane], a1 = xr[lane + 32];
        float s = a0 + a1, ss = a0 * a0 + a1 * a1;
#pragma unroll
        for (int o = 16; o; o >>= 1) {
            s  += __shfl_xor_sync(0xffffffffu, s, o);
            ss += __shfl_xor_sync(0xffffffffu, ss, o);
        }
        float m   = s * (1.f / 64.f);
        float var = fmaxf(ss * (1.f / 64.f) - m * m, 0.f);
        float inv = rsqrtf(var + 1e-5f);
        xsT[lane * 36 + r]        = (a0 - m) * inv * __ldg(&g1[lane])      + __ldg(&b1[lane]);
        xsT[(lane + 32) * 36 + r] = (a1 - m) * inv * __ldg(&g1[lane + 32]) + __ldg(&b1[lane + 32]);
    }
    __syncthreads();

    if (tid < 192) {
        int c = tid;
#pragma unroll
        for (int g = 0; g < 4; ++g) {
            float bb = bs[c];
            float acc[8];
#pragma unroll
            for (int i = 0; i < 8; ++i) acc[i] = bb;
#pragma unroll 4
            for (int k = 0; k < 64; ++k) {
                float wv  = ws[k * 192 + c];
                float4 xa = *(const float4*)&xsT[k * 36 + g * 8];
                float4 xb = *(const float4*)&xsT[k * 36 + g * 8 + 4];
                acc[0] = fmaf(xa.x, wv, acc[0]);
                acc[1] = fmaf(xa.y, wv, acc[1]);
                acc[2] = fmaf(xa.z, wv, acc[2]);
                acc[3] = fmaf(xa.w, wv, acc[3]);
                acc[4] = fmaf(xb.x, wv, acc[4]);
                acc[5] = fmaf(xb.y, wv, acc[5]);
                acc[6] = fmaf(xb.z, wv, acc[6]);
                acc[7] = fmaf(xb.w, wv, acc[7]);
            }
#pragma unroll
            for (int i = 0; i < 8; ++i)
                g_qkv[(size_t)(rowBase + g * 8 + i) * 192 + c] = acc[i];
        }
    }
}

// ---------------- k2a: bin points into 16^3 grid (counting sort) -----------------
// pass 0: unmasked points -> g_bpts + g_cellrange.  pass 1: all points -> g_qord.
__global__ void k2a_bins(const float* __restrict__ coords) {
    __shared__ unsigned int cnts[4096];
    __shared__ unsigned int starts[4096];
    __shared__ unsigned int wsum[32];
    int b = blockIdx.x, tid = threadIdx.x;           // 1024 threads
    const float* cb = coords + (size_t)b * Nn * 3;
    int lane = tid & 31, wid = tid >> 5;

    for (int pass = 0; pass < 2; ++pass) {
        for (int i = tid; i < 4096; i += 1024) cnts[i] = 0;
        __syncthreads();
        for (int i = tid; i < Nn; i += 1024) {
            if (pass == 0 && !g_mask[b * Nn + i]) continue;
            float x = cb[i * 3], y = cb[i * 3 + 1], z = cb[i * 3 + 2];
            int cx = min(15, (int)x), cy = min(15, (int)y), cz = min(15, (int)z);
            atomicAdd(&cnts[(cz * 16 + cy) * 16 + cx], 1u);
        }
        __syncthreads();
        // exclusive scan of 4096 counts (4 per thread)
        unsigned v0 = cnts[tid * 4], v1 = cnts[tid * 4 + 1],
                 v2 = cnts[tid * 4 + 2], v3 = cnts[tid * 4 + 3];
        unsigned tot = v0 + v1 + v2 + v3;
        unsigned inc = tot;
#pragma unroll
        for (int o = 1; o < 32; o <<= 1) {
            unsigned n = __shfl_up_sync(0xffffffffu, inc, o);
            if (lane >= o) inc += n;
        }
        if (lane == 31) wsum[wid] = inc;
        __syncthreads();
        if (wid == 0) {
            unsigned t = wsum[lane];
            unsigned i2 = t;
#pragma unroll
            for (int o = 1; o < 32; o <<= 1) {
                unsigned n = __shfl_up_sync(0xffffffffu, i2, o);
                if (lane >= o) i2 += n;
            }
            wsum[lane] = i2 - t;
        }
        __syncthreads();
        unsigned base = wsum[wid] + (inc - tot);
        unsigned s0 = base, s1 = base + v0, s2 = s1 + v1, s3 = s2 + v2;
        starts[tid * 4] = s0; starts[tid * 4 + 1] = s1;
        starts[tid * 4 + 2] = s2; starts[tid * 4 + 3] = s3;
        if (pass == 0) {
            g_cellrange[b * 4096 + tid * 4 + 0] = make_int2((int)s0, (int)v0);
            g_cellrange[b * 4096 + tid * 4 + 1] = make_int2((int)s1, (int)v1);
            g_cellrange[b * 4096 + tid * 4 + 2] = make_int2((int)s2, (int)v2);
            g_cellrange[b * 4096 + tid * 4 + 3] = make_int2((int)s3, (int)v3);
        }
        __syncthreads();
        for (int i = tid; i < Nn; i += 1024) {
            if (pass == 0 && !g_mask[b * Nn + i]) continue;
            float x = cb[i * 3], y = cb[i * 3 + 1], z = cb[i * 3 + 2];
            int cx = min(15, (int)x), cy = min(15, (int)y), cz = min(15, (int)z);
            unsigned pos = atomicAdd(&starts[(cz * 16 + cy) * 16 + cx], 1u);
            if (pass == 0) g_bpts[b * Nn + pos] = make_float4(x, y, z, __int_as_float(i));
            else           g_qord[b * Nn + pos] = i;
        }
        __syncthreads();
    }
}

// ---------------- k2b: exact KNN, WARP-per-query (lane-distributed cells) --------
// d' = |c|^2 - 2 q.c (shifted by -|q|^2; ordering preserved).
// Each lane keeps a private sorted top-10 of the candidates it scans; the global
// top-10 is a subset of the union of per-lane top-10s, merged by a 10-round
// lexicographic (d, idx) argmin warp reduction (lowest index wins ties).
// Shell bound: ring-s cells hold points >= (s-1) away, so shells with
// (s-1)^2 > d9_true contribute nothing.
__global__ void k2b_knn(const float* __restrict__ coords) {
    int lane = threadIdx.x & 31, warp = threadIdx.x >> 5;
    int b = blockIdx.y;
    int t = blockIdx.x * 8 + warp;                   // bin-ordered query slot
    int q = g_qord[b * Nn + t];
    const float* cb = coords + (size_t)b * Nn * 3;
    float qx = cb[q * 3], qy = cb[q * 3 + 1], qz = cb[q * 3 + 2];
    float qq = fmaf(qx, qx, fmaf(qy, qy, qz * qz));
    float nx = -2.f * qx, ny = -2.f * qy, nz = -2.f * qz;
    int qcx = min(15, (int)qx), qcy = min(15, (int)qy), qcz = min(15, (int)qz);

    const float4* bp = &g_bpts[b * Nn];
    const int2*   cr = &g_cellrange[b * 4096];

    float d[KNNk]; int id[KNNk];
#pragma unroll
    for (int i = 0; i < KNNk; ++i) { d[i] = 3.4e38f; id[i] = 0; }

    // phase 1: full 5x5x5 neighborhood (shells 0..2), cells distributed over lanes
    for (int c5 = lane; c5 < 125; c5 += 32) {
        int dz = c5 / 25 - 2, dy = (c5 / 5) % 5 - 2, dx = c5 % 5 - 2;
        int z = qcz + dz, y = qcy + dy, xx = qcx + dx;
        if ((unsigned)xx > 15u || (unsigned)y > 15u || (unsigned)z > 15u) continue;
        int2 rg = __ldg(&cr[(z * 16 + y) * 16 + xx]);
        int pe = rg.x + rg.y;
        for (int p = rg.x; p < pe; ++p) {
            float4 c = __ldg(&bp[p]);
            float cc = fmaf(c.x, c.x, fmaf(c.y, c.y, c.z * c.z));
            float dd = fmaf(nx, c.x, fmaf(ny, c.y, fmaf(nz, c.z, cc)));
            if (dd < d[KNNk - 1]) {
                float cv = dd; int ci = __float_as_int(c.w);
#pragma unroll
                for (int k = 0; k < KNNk; ++k) {
                    bool pr = cv < d[k];
                    float tf = d[k]; int ti = id[k];
                    d[k]  = pr ? cv : tf;
                    id[k] = pr ? ci : ti;
                    cv    = pr ? tf : cv;
                    ci    = pr ? ti : ci;
                }
            }
        }
    }

    // merge: 10 rounds of warp argmin over (d, idx); lane i keeps rank i
    float gdL = 3.4e38f; int gidL = 0; float gd9;
    {
        int head = 0;
#pragma unroll
        for (int i = 0; i < KNNk; ++i) {
            float mv = (head < KNNk) ? d[head] : 3.4e38f;
            int   mi = (head < KNNk) ? id[head] : 0x7fffffff;
#pragma unroll
            for (int o = 16; o; o >>= 1) {
                float ov = __shfl_xor_sync(0xffffffffu, mv, o);
                int   oi = __shfl_xor_sync(0xffffffffu, mi, o);
                if (ov < mv || (ov == mv && oi < mi)) { mv = ov; mi = oi; }
            }
            if (lane == i) { gdL = mv; gidL = mi; }
            if (head < KNNk && d[head] == mv && id[head] == mi) ++head;
        }
        gd9 = __shfl_sync(0xffffffffu, gdL, 9);
    }

    // phase 2: rare outer shells (corner queries with sparse 5x5x5)
    for (int s = 3; s < 16; ++s) {
        if ((float)((s - 1) * (s - 1)) > gd9 + qq) break;   // warp-uniform
        int w1 = 2 * s + 1, ncell = w1 * w1 * w1;
        bool added = false;
        for (int c5 = lane; c5 < ncell; c5 += 32) {
            int dz = c5 / (w1 * w1) - s, dy = (c5 / w1) % w1 - s, dx = c5 % w1 - s;
            int m = max(abs(dx), max(abs(dy), abs(dz)));
            if (m != s) continue;                            // ring only
            int z = qcz + dz, y = qcy + dy, xx = qcx + dx;
            if ((unsigned)xx > 15u || (unsigned)y > 15u || (unsigned)z > 15u) continue;
            int2 rg = __ldg(&cr[(z * 16 + y) * 16 + xx]);
            int pe = rg.x + rg.y;
            for (int p = rg.x; p < pe; ++p) {
                float4 c = __ldg(&bp[p]);
                float cc = fmaf(c.x, c.x, fmaf(c.y, c.y, c.z * c.z));
                float dd = fmaf(nx, c.x, fmaf(ny, c.y, fmaf(nz, c.z, cc)));
                if (dd < d[KNNk - 1]) {
                    added = true;
                    float cv = dd; int ci = __float_as_int(c.w);
#pragma unroll
                    for (int k = 0; k < KNNk; ++k) {
                        bool pr = cv < d[k];
                        float tf = d[k]; int ti = id[k];
                        d[k]  = pr ? cv : tf;
                        id[k] = pr ? ci : ti;
                        cv    = pr ? tf : cv;
                        ci    = pr ? ti : ci;
                    }
                }
            }
        }
        if (__any_sync(0xffffffffu, added)) {
            int head = 0;
#pragma unroll
            for (int i = 0; i < KNNk; ++i) {
                float mv = (head < KNNk) ? d[head] : 3.4e38f;
                int   mi = (head < KNNk) ? id[head] : 0x7fffffff;
#pragma unroll
                for (int o = 16; o; o >>= 1) {
                    float ov = __shfl_xor_sync(0xffffffffu, mv, o);
                    int   oi = __shfl_xor_sync(0xffffffffu, mi, o);
                    if (ov < mv || (ov == mv && oi < mi)) { mv = ov; mi = oi; }
                }
                if (lane == i) { gdL = mv; gidL = mi; }
                if (head < KNNk && d[head] == mv && id[head] == mi) ++head;
            }
            gd9 = __shfl_sync(0xffffffffu, gdL, 9);
        }
    }

    if (lane < KNNk) g_nbr[(size_t)(b * Nn + q) * KNNk + lane] = gidL;
}

// ---------------- k3: attention (64 rows / block, warp loops 8 rows) -------------
__global__ void k3_attn(const float* __restrict__ inputs,
                        const float* __restrict__ wproj, const float* __restrict__ bproj) {
    __shared__ float wp[4096];
    __shared__ float bp[64];
    __shared__ __align__(16) float qs[8][64];
    __shared__ float sc[8][40];
    __shared__ float swt[8][16];
    __shared__ int   sjg[8][16];
    __shared__ int   snb[8][KNNk];
    __shared__ float ovec[8][64];

    int tid = threadIdx.x, w = tid >> 5, lane = tid & 31;
    for (int i = tid; i < 4096; i += 256) wp[i] = wproj[i];
    if (tid < 64) bp[tid] = bproj[tid];
    __syncthreads();

    for (int r8 = 0; r8 < 8; ++r8) {
        int row  = blockIdx.x * 64 + w * 8 + r8;
        int base = row & ~(Nn - 1);

        const float* qr = &g_qkv[(size_t)row * 192];
        qs[w][lane]      = qr[lane];
        qs[w][lane + 32] = qr[lane + 32];
        if (lane < KNNk) snb[w][lane] = g_nbr[(size_t)row * KNNk + lane];
        __syncwarp();

        for (int t = lane; t < Hh * KNNk; t += 32) {
            int h = t / KNNk, j = t - h * KNNk;
            int jl = snb[w][j];
            const float* kp = &g_qkv[(size_t)(base + jl) * 192 + 64 + h * DH];
            const float* qp = &qs[w][h * DH];
            float4 k0 = *(const float4*)(kp);
            float4 k1 = *(const float4*)(kp + 4);
            float4 k2 = *(const float4*)(kp + 8);
            float4 k3 = *(const float4*)(kp + 12);
            float4 q0 = *(const float4*)(qp);
            float4 q1 = *(const float4*)(qp + 4);
            float4 q2 = *(const float4*)(qp + 8);
            float4 q3 = *(const float4*)(qp + 12);
            float acc = k0.x * q0.x + k0.y * q0.y + k0.z * q0.z + k0.w * q0.w
                      + k1.x * q1.x + k1.y * q1.y + k1.z * q1.z + k1.w * q1.w
                      + k2.x * q2.x + k2.y * q2.y + k2.z * q2.z + k2.w * q2.w
                      + k3.x * q3.x + k3.y * q3.y + k3.z * q3.z + k3.w * q3.w;
            float s = acc * 0.25f;
            if (!g_mask[base + jl]) s -= 1e9f;
            sc[w][t] = s;
        }
        __syncwarp();

        if (lane < Hh) {
            int h = lane;
            float bv0 = -3.4e38f, bv1 = -3.4e38f, bv2 = -3.4e38f, bv3 = -3.4e38f;
            int   bi0 = 0, bi1 = 0, bi2 = 0, bi3 = 0;
#pragma unroll
            for (int j = 0; j < KNNk; ++j) {
                float v = sc[w][h * KNNk + j]; int vi = j;
                if (v > bv0) { float t0 = bv0; int ti = bi0; bv0 = v; bi0 = vi; v = t0; vi = ti; }
                if (v > bv1) { float t0 = bv1; int ti = bi1; bv1 = v; bi1 = vi; v = t0; vi = ti; }
                if (v > bv2) { float t0 = bv2; int ti = bi2; bv2 = v; bi2 = vi; v = t0; vi = ti; }
                if (v > bv3) { float t0 = bv3; int ti = bi3; bv3 = v; bi3 = vi; v = t0; vi = ti; }
            }
            float e1 = __expf(bv1 - bv0), e2 = __expf(bv2 - bv0), e3 = __expf(bv3 - bv0);
            float inv = 1.f / (1.f + e1 + e2 + e3);
            swt[w][h * 4 + 0] = inv;
            swt[w][h * 4 + 1] = e1 * inv;
            swt[w][h * 4 + 2] = e2 * inv;
            swt[w][h * 4 + 3] = e3 * inv;
            sjg[w][h * 4 + 0] = base + snb[w][bi0];
            sjg[w][h * 4 + 1] = base + snb[w][bi1];
            sjg[w][h * 4 + 2] = base + snb[w][bi2];
            sjg[w][h * 4 + 3] = base + snb[w][bi3];
        }
        __syncwarp();

        {
            int c0 = lane, c1 = lane + 32;
            int h0 = c0 >> 4, h1 = c1 >> 4;
            float a0 = 0.f, a1 = 0.f;
#pragma unroll
            for (int s = 0; s < KSk; ++s) {
                a0 += swt[w][h0 * 4 + s] * g_qkv[(size_t)sjg[w][h0 * 4 + s] * 192 + 128 + c0];
                a1 += swt[w][h1 * 4 + s] * g_qkv[(size_t)sjg[w][h1 * 4 + s] * 192 + 128 + c1];
            }
            ovec[w][c0] = a0; ovec[w][c1] = a1;
        }
        __syncwarp();

        {
            float acc0 = bp[lane], acc1 = bp[lane + 32];
#pragma unroll 4
            for (int k = 0; k < 64; ++k) {
                float ov = ovec[w][k];
                acc0 = fmaf(ov, wp[k * 64 + lane], acc0);
                acc1 = fmaf(ov, wp[k * 64 + lane + 32], acc1);
            }
            float half0 = g_mask[row] ? 0.5f : 0.f;
            const float* ir = inputs + (size_t)row * 64;
            g_x[(size_t)row * 64 + lane]      = fmaf(half0, acc0, ir[lane]);
            g_x[(size_t)row * 64 + lane + 32] = fmaf(half0, acc1, ir[lane + 32]);
        }
        __syncwarp();
    }
}

// ---------------- k4: LN2 + MLP (64 rows / block, 512 threads) -------------------
__global__ void k4_mlp(const float* __restrict__ g2, const float* __restrict__ b2,
                       const float* __restrict__ w1, const float* __restrict__ b1,
                       const float* __restrict__ w2, const float* __restrict__ b2o,
                       float* __restrict__ out) {
    extern __shared__ float sm4[];
    float* w1s = sm4;             // 16384 = 64*256
    float* w2s = w1s + 16384;     // 16384 = 256*64
    float* b1s = w2s + 16384;     // 256
    float* xsT = b1s + 256;       // 64 * 68
    float* h1T = xsT + 4352;      // 256 * 68
    int tid = threadIdx.x;        // 512 threads
    int rowBase = blockIdx.x * 64;

    for (int i = tid; i < 16384; i += 512) { w1s[i] = w1[i]; w2s[i] = w2[i]; }
    if (tid < 256) b1s[tid] = b1[tid];

    int w = tid >> 5, lane = tid & 31;   // 16 warps x 4 rows = 64 rows
#pragma unroll
    for (int rr = 0; rr < 4; ++rr) {
        int r = w * 4 + rr;
        const float* xr = &g_x[(size_t)(rowBase + r) * 64];
        float a0 = xr[lane], a1 = xr[lane + 32];
        float s = a0 + a1, ss = a0 * a0 + a1 * a1;
#pragma unroll
        for (int o = 16; o; o >>= 1) {
            s  += __shfl_xor_sync(0xffffffffu, s, o);
            ss += __shfl_xor_sync(0xffffffffu, ss, o);
        }
        float m   = s * (1.f / 64.f);
        float var = fmaxf(ss * (1.f / 64.f) - m * m, 0.f);
        float inv = rsqrtf(var + 1e-5f);
        xsT[lane * 68 + r]        = (a0 - m) * inv * __ldg(&g2[lane])      + __ldg(&b2[lane]);
        xsT[(lane + 32) * 68 + r] = (a1 - m) * inv * __ldg(&g2[lane + 32]) + __ldg(&b2[lane + 32]);
    }
    __syncthreads();

    // h1[m][r] = gelu(xhat @ w1 + b1); thread = (col m, row-half), 4 groups of 8 rows
    {
        int mcol = tid & 255, half = tid >> 8;
#pragma unroll
        for (int g = 0; g < 4; ++g) {
            int r0 = half * 32 + g * 8;
            float bb = b1s[mcol];
            float acc[8];
#pragma unroll
            for (int i = 0; i < 8; ++i) acc[i] = bb;
#pragma unroll 4
            for (int k = 0; k < 64; ++k) {
                float wv  = w1s[k * 256 + mcol];
                float4 xa = *(const float4*)&xsT[k * 68 + r0];
                float4 xb = *(const float4*)&xsT[k * 68 + r0 + 4];
                acc[0] = fmaf(xa.x, wv, acc[0]);
                acc[1] = fmaf(xa.y, wv, acc[1]);
                acc[2] = fmaf(xa.z, wv, acc[2]);
                acc[3] = fmaf(xa.w, wv, acc[3]);
                acc[4] = fmaf(xb.x, wv, acc[4]);
                acc[5] = fmaf(xb.y, wv, acc[5]);
                acc[6] = fmaf(xb.z, wv, acc[6]);
                acc[7] = fmaf(xb.w, wv, acc[7]);
            }
#pragma unroll
            for (int i = 0; i < 8; ++i) {
                float xv = acc[i];
                float u = 0.7978845608028654f * (xv + 0.044715f * xv * xv * xv);
                float th;
                asm("tanh.approx.f32 %0, %1;" : "=f"(th) : "f"(u));
                h1T[mcol * 68 + r0 + i] = 0.5f * xv * (1.f + th);
            }
        }
    }
    __syncthreads();

    // h2[r][c] = h1 @ w2 + b2; out = 0.5*h2 + x
    {
        int c = tid & 63, rg = tid >> 6;   // 8 row-groups of 8
        float bb = __ldg(&b2o[c]);
        float acc[8];
#pragma unroll
        for (int i = 0; i < 8; ++i) acc[i] = bb;
#pragma unroll 2
        for (int k = 0; k < 256; ++k) {
            float wv  = w2s[k * 64 + c];
            float4 ha = *(const float4*)&h1T[k * 68 + rg * 8];
            float4 hb = *(const float4*)&h1T[k * 68 + rg * 8 + 4];
            acc[0] = fmaf(ha.x, wv, acc[0]);
            acc[1] = fmaf(ha.y, wv, acc[1]);
            acc[2] = fmaf(ha.z, wv, acc[2]);
            acc[3] = fmaf(ha.w, wv, acc[3]);
            acc[4] = fmaf(hb.x, wv, acc[4]);
            acc[5] = fmaf(hb.y, wv, acc[5]);
            acc[6] = fmaf(hb.z, wv, acc[6]);
            acc[7] = fmaf(hb.w, wv, acc[7]);
        }
#pragma unroll
        for (int i = 0; i < 8; ++i) {
            size_t row = (size_t)rowBase + rg * 8 + i;
            out[row * 64 + c] = fmaf(0.5f, acc[i], g_x[row * 64 + c]);
        }
    }
}

// ---------------- launch ----------------
extern "C" void kernel_launch(void* const* d_in, const int* in_sizes, int n_in,
                              void* d_out, int out_size) {
    (void)in_sizes; (void)n_in; (void)out_size;
    const float* inputs = (const float*)d_in[0];
    const float* coords = (const float*)d_in[1];
    const void*  maskp  = d_in[2];
    const float* ln1g   = (const float*)d_in[3];
    const float* ln1b   = (const float*)d_in[4];
    const float* ln2g   = (const float*)d_in[5];
    const float* ln2b   = (const float*)d_in[6];
    const float* wqkv   = (const float*)d_in[7];
    const float* bqkv   = (const float*)d_in[8];
    const float* wproj  = (const float*)d_in[9];
    const float* bproj  = (const float*)d_in[10];
    const float* w1     = (const float*)d_in[11];
    const float* b1     = (const float*)d_in[12];
    const float* w2     = (const float*)d_in[13];
    const float* b2     = (const float*)d_in[14];
    float* out = (float*)d_out;

    cudaFuncSetAttribute(k1_ln_qkv, cudaFuncAttributeMaxDynamicSharedMemorySize, 59136);
    cudaFuncSetAttribute(k4_mlp,    cudaFuncAttributeMaxDynamicSharedMemorySize, 219136);

    k0_mask<<<64, 256>>>(maskp);
    k2a_bins<<<4, 1024>>>(coords);
    k1_ln_qkv<<<512, 256, 59136>>>(inputs, ln1g, ln1b, wqkv, bqkv);
    k2b_knn<<<dim3(512, 4), 256>>>(coords);
    k3_attn<<<256, 256>>>(inputs, wproj, bproj);
    k4_mlp<<<256, 512, 219136>>>(ln2g, ln2b, w1, b1, w2, b2, out);
}